// round 10
// baseline (speedup 1.0000x reference)
#include <cuda_runtime.h>
#include <cuda_fp16.h>
#include <math.h>
#include <stdint.h>

// ---------------------------------------------------------------------------
// CortexBlock on GB300 (compute_103 pipeline => mma.sync HMMA path)
// B=4, T=2048, D=1024, H=16, Dh=64, R=16
// R8 kernels (proven 1516us) + T-chunked 2-stream pipeline: scan chunk c
// overlaps QKV chunk c+1; O chunk c overlaps later scan chunks.
// ---------------------------------------------------------------------------

#define D_MODEL 1024
#define N_HEADS 16
#define D_HEAD  64
#define RANK    16
#define DECAY   0.95f
#define ALPHA_MAX 0.05f
#define BETA    0.01f

#define BB 4
#define TT 2048
#define BT (BB*TT)   // 8192
#define NCHUNKS 4
#define TC (TT/NCHUNKS)   // 512

// ---------------- scratch (static device globals; no allocs allowed) -------
__device__ __align__(256) __half g_xh[BT * D_MODEL];
__device__ __align__(256) __half g_w[4 * D_MODEL * D_MODEL];   // Wq,Wk,Wv,Wo fp16
__device__ __align__(256) __half g_yh[BT * D_MODEL];
__device__ __align__(256) float g_q[BT * D_MODEL];
__device__ __align__(256) float g_k[BT * D_MODEL];
__device__ __align__(256) float g_v[BT * D_MODEL];
__device__ __align__(256) float g_alpha[BT * N_HEADS];
// scan state carried across T-chunks: [bh][d][r]
__device__ __align__(256) float g_Us[BB * N_HEADS * D_HEAD * RANK];
__device__ __align__(256) float g_Vs[BB * N_HEADS * D_HEAD * RANK];

// ---------------- small asm helpers ----------------------------------------
__device__ __forceinline__ uint32_t smem_u32(const void* p) {
    uint32_t a;
    asm("{ .reg .u64 t; cvta.to.shared.u64 t, %1; cvt.u32.u64 %0, t; }"
        : "=r"(a) : "l"(p));
    return a;
}
__device__ __forceinline__ void cp_async16(uint32_t daddr, const void* gaddr) {
    asm volatile("cp.async.cg.shared.global [%0], [%1], 16;"
                 :: "r"(daddr), "l"(gaddr) : "memory");
}
#define CP_COMMIT()  asm volatile("cp.async.commit_group;" ::: "memory")
#define CP_WAIT(n)   asm volatile("cp.async.wait_group %0;" :: "n"(n) : "memory")

__device__ __forceinline__ void ldsm_x4(uint32_t (&r)[4], uint32_t addr) {
    asm volatile("ldmatrix.sync.aligned.m8n8.x4.shared.b16 {%0,%1,%2,%3}, [%4];"
                 : "=r"(r[0]), "=r"(r[1]), "=r"(r[2]), "=r"(r[3]) : "r"(addr));
}
__device__ __forceinline__ void mma_16816_f16(float (&d)[4], const uint32_t (&a)[4],
                                              uint32_t b0, uint32_t b1) {
    asm volatile(
        "mma.sync.aligned.m16n8k16.row.col.f32.f16.f16.f32 "
        "{%0,%1,%2,%3}, {%4,%5,%6,%7}, {%8,%9}, {%0,%1,%2,%3};"
        : "+f"(d[0]), "+f"(d[1]), "+f"(d[2]), "+f"(d[3])
        : "r"(a[0]), "r"(a[1]), "r"(a[2]), "r"(a[3]), "r"(b0), "r"(b1));
}

// ---------------------------------------------------------------------------
// fp16 single-pass GEMM (R8 config): C[M,N](fp32) = A[M,K] * W[N,K]^T
// CTA tile 128x128, K-chunk 64, 4-stage cp.async, 1 barrier/chunk.
// Rows chunked by T: blockIdx.y -> (b = y>>2, blk = y&3);
// rowBase = b*TT + tBase + blk*128.   grid.y = 16 per T-chunk.
// ---------------------------------------------------------------------------
#define GM 128
#define GN 128
#define GKC 64
#define AST 72
#define TILE_HALVES (GM * AST)            // 9216 halves = 18432 B
#define TILE_BYTES  (TILE_HALVES * 2)
#define STAGE_BYTES (2 * TILE_BYTES)      // 36864
#define NSTAGE 4
#define GEMM_SMEM_BYTES (NSTAGE * STAGE_BYTES)   // 147456

__global__ __launch_bounds__(256, 1) void gemm_f16(
    const __half* __restrict__ A, const __half* __restrict__ Wbase,
    float* __restrict__ C0, float* __restrict__ C1, float* __restrict__ C2,
    int tBase, int N, int K)
{
    extern __shared__ __half smem[];

    const int tid  = threadIdx.x;
    const int wid  = tid >> 5;
    const int lane = tid & 31;
    const int rowBase = (blockIdx.y >> 2) * TT + tBase + (blockIdx.y & 3) * GM;
    const int colBase = blockIdx.x * GN;
    const int z = blockIdx.z;

    const __half* Bw = Wbase + (size_t)z * D_MODEL * D_MODEL;
    float* C = (z == 0) ? C0 : (z == 1) ? C1 : C2;

    const int wm = (wid >> 2) * 64;
    const int wn = (wid & 3) * 32;

    const uint32_t smBase = smem_u32(smem);

    float acc[4][4][4];
#pragma unroll
    for (int i = 0; i < 4; i++)
#pragma unroll
        for (int j = 0; j < 4; j++)
#pragma unroll
            for (int c = 0; c < 4; c++) acc[i][j][c] = 0.0f;

    const int aRow = lane & 15;
    const int aKo  = (lane >> 4) * 8;
    const int bNo  = ((lane >> 4) << 3) + (lane & 7);
    const int bKo  = ((lane >> 3) & 1) * 8;

    const int NCH = K / GKC;              // 16

    auto issue = [&](int ci) {
        const int k0 = ci * GKC;
        const uint32_t stage = smBase + (uint32_t)(ci % NSTAGE) * STAGE_BYTES;
#pragma unroll
        for (int i = 0; i < 4; i++) {
            int L = tid + (i << 8);
            int row = L >> 3;
            int seg = L & 7;
            uint32_t off = (uint32_t)row * (AST * 2) + seg * 16;
            cp_async16(stage + off,
                       A + (size_t)(rowBase + row) * K + k0 + seg * 8);
            cp_async16(stage + TILE_BYTES + off,
                       Bw + (size_t)(colBase + row) * K + k0 + seg * 8);
        }
        CP_COMMIT();
    };

    issue(0);
    issue(1);
    issue(2);

    for (int ci = 0; ci < NCH; ci++) {
        CP_WAIT(2);
        __syncthreads();
        if (ci + 3 < NCH) issue(ci + 3);
        else CP_COMMIT();

        const uint32_t stage  = smBase + (uint32_t)(ci % NSTAGE) * STAGE_BYTES;
        const uint32_t bBase0 = stage + TILE_BYTES;

#pragma unroll
        for (int ks = 0; ks < 4; ks++) {
            uint32_t Ar[4][4];
#pragma unroll
            for (int mi = 0; mi < 4; mi++) {
                uint32_t addr = stage + (uint32_t)(wm + mi * 16 + aRow) * (AST * 2)
                              + (uint32_t)(ks * 16 + aKo) * 2;
                ldsm_x4(Ar[mi], addr);
            }
            uint32_t Br[2][4];
#pragma unroll
            for (int ni = 0; ni < 2; ni++) {
                uint32_t addr = bBase0 + (uint32_t)(wn + ni * 16 + bNo) * (AST * 2)
                              + (uint32_t)(ks * 16 + bKo) * 2;
                ldsm_x4(Br[ni], addr);
            }
#pragma unroll
            for (int mi = 0; mi < 4; mi++)
#pragma unroll
                for (int j = 0; j < 4; j++)
                    mma_16816_f16(acc[mi][j], Ar[mi],
                                  Br[j >> 1][(j & 1) * 2], Br[j >> 1][(j & 1) * 2 + 1]);
        }
    }

#pragma unroll
    for (int mi = 0; mi < 4; mi++) {
        const int row0 = rowBase + wm + mi * 16 + (lane >> 2);
#pragma unroll
        for (int j = 0; j < 4; j++) {
            const int col = colBase + wn + j * 8 + (lane & 3) * 2;
            *reinterpret_cast<float2*>(C + (size_t)row0 * N + col) =
                make_float2(acc[mi][j][0], acc[mi][j][1]);
            *reinterpret_cast<float2*>(C + (size_t)(row0 + 8) * N + col) =
                make_float2(acc[mi][j][2], acc[mi][j][3]);
        }
    }
}

// ---------------------------------------------------------------------------
// Fused x->fp16 convert + alpha (R8). Block = 16 rows, 512 threads.
// ---------------------------------------------------------------------------
__global__ __launch_bounds__(512) void cvtx_alpha_kernel(
    const float* __restrict__ x, const float* __restrict__ Wa,
    const float* __restrict__ ba, const float* __restrict__ m_gate,
    const float* __restrict__ ascale,
    __half* __restrict__ xh, float* __restrict__ alpha)
{
    extern __shared__ float xs[];        // [16][1024]
    const int tid  = threadIdx.x;
    const int warp = tid >> 5;
    const int lane = tid & 31;
    const int rowBase = blockIdx.x * 16;

    const float4* xg = reinterpret_cast<const float4*>(x + (size_t)rowBase * D_MODEL);
#pragma unroll
    for (int it = 0; it < 8; it++) {
        int i = tid + it * 512;
        float4 v = xg[i];
        reinterpret_cast<float4*>(xs)[i] = v;
        __half2* ph = reinterpret_cast<__half2*>(xh + (size_t)rowBase * D_MODEL + i * 4);
        ph[0] = __half2(__float2half_rn(v.x), __float2half_rn(v.y));
        ph[1] = __half2(__float2half_rn(v.z), __float2half_rn(v.w));
    }
    __syncthreads();

    float wa[32];
#pragma unroll
    for (int i = 0; i < 32; i++)
        wa[i] = Wa[(size_t)warp * D_MODEL + i * 32 + lane];
    const float bw = ba[warp];

#pragma unroll 4
    for (int row = 0; row < 16; row++) {
        const float* xr = xs + row * D_MODEL;
        float s = 0.0f;
#pragma unroll
        for (int i = 0; i < 32; i++)
            s = fmaf(wa[i], xr[i * 32 + lane], s);
#pragma unroll
        for (int off = 16; off; off >>= 1)
            s += __shfl_xor_sync(0xFFFFFFFFu, s, off);
        if (lane == 0) {
            const int r = rowBase + row;
            float sg = __fdividef(1.0f, 1.0f + __expf(-(s + bw)));
            float a = sg * m_gate[r] * ascale[(size_t)r * N_HEADS + warp];
            alpha[(size_t)r * N_HEADS + warp] = fminf(a, ALPHA_MAX);
        }
    }
}

// ---------------------------------------------------------------------------
// Round all 4 weight matrices to fp16 in one launch.
// ---------------------------------------------------------------------------
__global__ __launch_bounds__(256) void cvt4_kernel(
    const float* __restrict__ W0, const float* __restrict__ W1,
    const float* __restrict__ W2, const float* __restrict__ W3,
    __half* __restrict__ out)
{
    const int i = blockIdx.x * 256 + threadIdx.x;
    const int sel = i >> 20;
    const int off = i & ((1 << 20) - 1);
    const float* src = (sel == 0) ? W0 : (sel == 1) ? W1 : (sel == 2) ? W2 : W3;
    out[i] = __float2half_rn(src[off]);
}

// ---------------------------------------------------------------------------
// Scan chunk [t0, t0+TC) — R8 scan body with state load/store.
// Block = (b,h); 64 threads (thread = d). 1 barrier/step.
// ---------------------------------------------------------------------------
__global__ __launch_bounds__(64) void scan_chunk(
    const float* __restrict__ q, const float* __restrict__ k,
    const float* __restrict__ v, const float* __restrict__ alpha,
    __half* __restrict__ yh, float* __restrict__ Us, float* __restrict__ Vs,
    int t0)
{
    const int bh = blockIdx.x;
    const int b = bh / N_HEADS;
    const int h = bh % N_HEADS;
    const int d = threadIdx.x;
    const int warp = d >> 5;
    const int lane = d & 31;

    float* stU = Us + ((size_t)bh * D_HEAD + d) * RANK;
    float* stV = Vs + ((size_t)bh * D_HEAD + d) * RANK;

    float U[RANK], Vv[RANK];
    if (t0 == 0) {
#pragma unroll
        for (int r = 0; r < RANK; r++) { U[r] = 0.0f; Vv[r] = 0.0f; }
    } else {
#pragma unroll
        for (int r = 0; r < RANK; r++) { U[r] = stU[r]; Vv[r] = stV[r]; }
    }

    __shared__ float  sm_ku[2][16][2];
    __shared__ float2 sm_sc[2][2];

    const int l4 = lane & 15;
    const int rIdx = ((l4 & 1) << 3) | ((l4 & 2) << 1) | ((l4 & 4) >> 1) | ((l4 & 8) >> 3);

    const size_t strideT = (size_t)N_HEADS * D_HEAD;   // 1024
    size_t idx = ((size_t)(b * TT + t0)) * strideT + h * D_HEAD + d;
    const size_t abase = (size_t)(b * TT) * N_HEADS + h;

    float qt = q[idx], kt = k[idx], vt = v[idx];
    float a  = alpha[abase + (size_t)t0 * N_HEADS];

    float sp0 = 0.f, sp1 = 0.f;
    float vprev = 0.f, kfprev = 0.f;
    size_t idxprev = idx;

    const int tEnd = t0 + TC;
    for (int t = t0; t < tEnd; t++) {
        const int buf = t & 1;
        const size_t nidx = idx + strideT;
        float nq = 0.f, nk = 0.f, nv = 0.f, na = 0.f;
        if (t + 1 < tEnd) {
            nq = q[nidx]; nk = k[nidx]; nv = v[nidx];
            na = alpha[abase + (size_t)(t + 1) * N_HEADS];
        }

        const float ktd = kt * DECAY;
        float p[RANK];
#pragma unroll
        for (int r = 0; r < RANK; r++) p[r] = ktd * U[r];

#pragma unroll
        for (int s = 1, cnt = 8; s <= 8; s <<= 1, cnt >>= 1) {
            const bool hi = (lane & s) != 0;
#pragma unroll
            for (int i = 0; i < cnt; i++) {
                float lo_v = p[i], hi_v = p[i + cnt];
                float send = hi ? lo_v : hi_v;
                float recv = __shfl_xor_sync(0xFFFFFFFFu, send, s);
                p[i] = (hi ? hi_v : lo_v) + recv;
            }
        }
        float vr = p[0] + __shfl_xor_sync(0xFFFFFFFFu, p[0], 16);

#pragma unroll
        for (int r = 0; r < RANK; r++) { U[r] *= DECAY; Vv[r] *= DECAY; }

        sm_ku[buf][rIdx][warp] = vr;
        if (lane == 0) sm_sc[buf][warp] = make_float2(sp0, sp1);
        __syncthreads();

        float ku[RANK];
#pragma unroll
        for (int r = 0; r < RANK; r++) {
            float2 t2 = *reinterpret_cast<const float2*>(&sm_ku[buf][r][0]);
            ku[r] = t2.x + t2.y;
        }

        const float ak = a * kt;
        const float av = a * vt;
        float kfp[4] = {0.f, 0.f, 0.f, 0.f};
#pragma unroll
        for (int r = 0; r < RANK; r++) {
            float u = fmaf(ak, ku[r], U[r]);
            float w = fmaf(av, ku[r], Vv[r]);
            u -= BETA * fminf(fmaxf(u, -1.0f), 1.0f);
            w -= BETA * fminf(fmaxf(w, -1.0f), 1.0f);
            U[r] = u;
            Vv[r] = w;
            kfp[r & 3] = fmaf(u, w, kfp[r & 3]);
        }
        const float kf = (kfp[0] + kfp[1]) + (kfp[2] + kfp[3]);

        if (t > t0) {
            float2 w0 = sm_sc[buf][0];
            float2 w1 = sm_sc[buf][1];
            const float S0 = w0.x + w1.x;
            const float S1 = w0.y + w1.y;
            const float m1 = __fdividef(1.0f, 1.0f + __expf(S0 - S1));
            yh[idxprev] = __float2half_rn((1.0f - m1) * vprev + m1 * kfprev);
        }

        const float qn = qt * 0.125f;
        float s0 = qn * kt;
        float s1 = qn * kf;
#pragma unroll
        for (int off = 16; off; off >>= 1) {
            s0 += __shfl_xor_sync(0xFFFFFFFFu, s0, off);
            s1 += __shfl_xor_sync(0xFFFFFFFFu, s1, off);
        }
        sp0 = s0; sp1 = s1;
        vprev = vt; kfprev = kf; idxprev = idx;

        qt = nq; kt = nk; vt = nv; a = na;
        idx = nidx;
    }

    // tail: finalize last step of this chunk
    if (lane == 0) sm_sc[tEnd & 1][warp] = make_float2(sp0, sp1);
    __syncthreads();
    {
        float2 w0 = sm_sc[tEnd & 1][0];
        float2 w1 = sm_sc[tEnd & 1][1];
        const float S0 = w0.x + w1.x;
        const float S1 = w0.y + w1.y;
        const float m1 = __fdividef(1.0f, 1.0f + __expf(S0 - S1));
        yh[idxprev] = __float2half_rn((1.0f - m1) * vprev + m1 * kfprev);
    }

    // persist state for next chunk
#pragma unroll
    for (int r = 0; r < RANK; r++) { stU[r] = U[r]; stV[r] = Vv[r]; }
}

// ---------------------------------------------------------------------------
// Stream/event objects: created at static-init time (before harness memory
// baselines). Host-side objects only; no device allocation APIs used.
// ---------------------------------------------------------------------------
struct PipeObjs {
    cudaStream_t s1;
    cudaEvent_t qe[NCHUNKS], se[NCHUNKS];
    PipeObjs() {
        cudaStreamCreateWithFlags(&s1, cudaStreamNonBlocking);
        for (int i = 0; i < NCHUNKS; i++) {
            cudaEventCreateWithFlags(&qe[i], cudaEventDisableTiming);
            cudaEventCreateWithFlags(&se[i], cudaEventDisableTiming);
        }
    }
};
static PipeObjs g_pipe;

// ---------------------------------------------------------------------------
// Launch: prep -> [QKV(c) -> scan(c) (stream1) -> O(c)] pipelined via events.
// ---------------------------------------------------------------------------
extern "C" void kernel_launch(void* const* d_in, const int* in_sizes, int n_in,
                              void* d_out, int out_size)
{
    const float* x      = (const float*)d_in[0];
    const float* m_gate = (const float*)d_in[1];
    const float* ascale = (const float*)d_in[2];
    const float* Wq     = (const float*)d_in[3];
    const float* Wk     = (const float*)d_in[4];
    const float* Wv     = (const float*)d_in[5];
    const float* Wo     = (const float*)d_in[6];
    const float* Wa     = (const float*)d_in[7];
    const float* ba     = (const float*)d_in[8];
    // d_in[9] = mix_logit: cancels in the 2-way softmax; unused.
    float* out = (float*)d_out;

    __half *xh, *wf, *yh;
    float *dq, *dk, *dv, *da, *dUs, *dVs;
    cudaGetSymbolAddress((void**)&xh, g_xh);
    cudaGetSymbolAddress((void**)&wf, g_w);
    cudaGetSymbolAddress((void**)&yh, g_yh);
    cudaGetSymbolAddress((void**)&dq, g_q);
    cudaGetSymbolAddress((void**)&dk, g_k);
    cudaGetSymbolAddress((void**)&dv, g_v);
    cudaGetSymbolAddress((void**)&da, g_alpha);
    cudaGetSymbolAddress((void**)&dUs, g_Us);
    cudaGetSymbolAddress((void**)&dVs, g_Vs);

    const int DW = D_MODEL * D_MODEL;

    static bool attr_set = false;
    if (!attr_set) {
        cudaFuncSetAttribute(gemm_f16,
                             cudaFuncAttributeMaxDynamicSharedMemorySize, GEMM_SMEM_BYTES);
        cudaFuncSetAttribute(cvtx_alpha_kernel,
                             cudaFuncAttributeMaxDynamicSharedMemorySize, 16 * D_MODEL * 4);
        attr_set = true;
    }

    // prep (default stream)
    cvtx_alpha_kernel<<<BT / 16, 512, 16 * D_MODEL * 4>>>(
        x, Wa, ba, m_gate, ascale, xh, da);
    cvt4_kernel<<<(4 * DW) / 256, 256>>>(Wq, Wk, Wv, Wo, wf);

    // QKV chunks on default stream, each followed by an event
    for (int c = 0; c < NCHUNKS; c++) {
        dim3 g(D_MODEL / GN, (BB * TC) / GM, 3);   // (8, 16, 3)
        gemm_f16<<<g, 256, GEMM_SMEM_BYTES>>>(xh, wf, dq, dk, dv,
                                              c * TC, D_MODEL, D_MODEL);
        cudaEventRecord(g_pipe.qe[c], 0);
    }

    // scan chunks on stream1 (serial there; each waits its QKV event)
    for (int c = 0; c < NCHUNKS; c++) {
        cudaStreamWaitEvent(g_pipe.s1, g_pipe.qe[c], 0);
        scan_chunk<<<BB * N_HEADS, 64, 0, g_pipe.s1>>>(
            dq, dk, dv, da, yh, dUs, dVs, c * TC);
        cudaEventRecord(g_pipe.se[c], g_pipe.s1);
    }

    // O chunks on default stream; each waits its scan event (joins stream1)
    for (int c = 0; c < NCHUNKS; c++) {
        cudaStreamWaitEvent(0, g_pipe.se[c], 0);
        dim3 g(D_MODEL / GN, (BB * TC) / GM, 1);   // (8, 16, 1)
        gemm_f16<<<g, 256, GEMM_SMEM_BYTES>>>(yh, wf + (size_t)3 * DW,
                                              out, out, out,
                                              c * TC, D_MODEL, D_MODEL);
    }
}

// round 11
// speedup vs baseline: 2.1787x; 2.1787x over previous
#include <cuda_runtime.h>
#include <cuda_fp16.h>
#include <math.h>
#include <stdint.h>

// ---------------------------------------------------------------------------
// CortexBlock on GB300 (compute_103 pipeline => mma.sync HMMA path)
// B=4, T=2048, D=1024, H=16, Dh=64, R=16
// R8 GEMMs (fp16 single-pass) + scan with cp.async smem staging of q/k/v/alpha
// (16-step chunks, double-buffered, 2 chunks in flight) -> memory latency off
// the recurrence critical path.
// ---------------------------------------------------------------------------

#define D_MODEL 1024
#define N_HEADS 16
#define D_HEAD  64
#define RANK    16
#define DECAY   0.95f
#define ALPHA_MAX 0.05f
#define BETA    0.01f

#define BB 4
#define TT 2048
#define BT (BB*TT)   // 8192

// ---------------- scratch (static device globals; no allocs allowed) -------
__device__ __align__(256) __half g_xh[BT * D_MODEL];
__device__ __align__(256) __half g_w[4 * D_MODEL * D_MODEL];   // Wq,Wk,Wv,Wo fp16
__device__ __align__(256) __half g_yh[BT * D_MODEL];
__device__ __align__(256) float g_q[BT * D_MODEL];
__device__ __align__(256) float g_k[BT * D_MODEL];
__device__ __align__(256) float g_v[BT * D_MODEL];
__device__ __align__(256) float g_alpha[BT * N_HEADS];

// ---------------- small asm helpers ----------------------------------------
__device__ __forceinline__ uint32_t smem_u32(const void* p) {
    uint32_t a;
    asm("{ .reg .u64 t; cvta.to.shared.u64 t, %1; cvt.u32.u64 %0, t; }"
        : "=r"(a) : "l"(p));
    return a;
}
__device__ __forceinline__ void cp_async16(uint32_t daddr, const void* gaddr) {
    asm volatile("cp.async.cg.shared.global [%0], [%1], 16;"
                 :: "r"(daddr), "l"(gaddr) : "memory");
}
__device__ __forceinline__ void cp_async4(uint32_t daddr, const void* gaddr) {
    asm volatile("cp.async.ca.shared.global [%0], [%1], 4;"
                 :: "r"(daddr), "l"(gaddr) : "memory");
}
#define CP_COMMIT()  asm volatile("cp.async.commit_group;" ::: "memory")
#define CP_WAIT(n)   asm volatile("cp.async.wait_group %0;" :: "n"(n) : "memory")

__device__ __forceinline__ void ldsm_x4(uint32_t (&r)[4], uint32_t addr) {
    asm volatile("ldmatrix.sync.aligned.m8n8.x4.shared.b16 {%0,%1,%2,%3}, [%4];"
                 : "=r"(r[0]), "=r"(r[1]), "=r"(r[2]), "=r"(r[3]) : "r"(addr));
}
__device__ __forceinline__ void mma_16816_f16(float (&d)[4], const uint32_t (&a)[4],
                                              uint32_t b0, uint32_t b1) {
    asm volatile(
        "mma.sync.aligned.m16n8k16.row.col.f32.f16.f16.f32 "
        "{%0,%1,%2,%3}, {%4,%5,%6,%7}, {%8,%9}, {%0,%1,%2,%3};"
        : "+f"(d[0]), "+f"(d[1]), "+f"(d[2]), "+f"(d[3])
        : "r"(a[0]), "r"(a[1]), "r"(a[2]), "r"(a[3]), "r"(b0), "r"(b1));
}

// ---------------------------------------------------------------------------
// fp16 single-pass GEMM (R8 config): C[M,N](fp32) = A[M,K] * W[N,K]^T
// CTA tile 128x128, K-chunk 64, 4-stage cp.async, 1 barrier/chunk.
// ---------------------------------------------------------------------------
#define GM 128
#define GN 128
#define GKC 64
#define AST 72
#define TILE_HALVES (GM * AST)            // 9216 halves = 18432 B
#define TILE_BYTES  (TILE_HALVES * 2)
#define STAGE_BYTES (2 * TILE_BYTES)      // 36864
#define NSTAGE 4
#define GEMM_SMEM_BYTES (NSTAGE * STAGE_BYTES)   // 147456

__global__ __launch_bounds__(256, 1) void gemm_f16(
    const __half* __restrict__ A, const __half* __restrict__ Wbase,
    float* __restrict__ C0, float* __restrict__ C1, float* __restrict__ C2,
    int M, int N, int K)
{
    extern __shared__ __half smem[];

    const int tid  = threadIdx.x;
    const int wid  = tid >> 5;
    const int lane = tid & 31;
    const int rowBase = blockIdx.y * GM;
    const int colBase = blockIdx.x * GN;
    const int z = blockIdx.z;

    const __half* Bw = Wbase + (size_t)z * D_MODEL * D_MODEL;
    float* C = (z == 0) ? C0 : (z == 1) ? C1 : C2;

    const int wm = (wid >> 2) * 64;
    const int wn = (wid & 3) * 32;

    const uint32_t smBase = smem_u32(smem);

    float acc[4][4][4];
#pragma unroll
    for (int i = 0; i < 4; i++)
#pragma unroll
        for (int j = 0; j < 4; j++)
#pragma unroll
            for (int c = 0; c < 4; c++) acc[i][j][c] = 0.0f;

    const int aRow = lane & 15;
    const int aKo  = (lane >> 4) * 8;
    const int bNo  = ((lane >> 4) << 3) + (lane & 7);
    const int bKo  = ((lane >> 3) & 1) * 8;

    const int NCH = K / GKC;              // 16

    auto issue = [&](int ci) {
        const int k0 = ci * GKC;
        const uint32_t stage = smBase + (uint32_t)(ci % NSTAGE) * STAGE_BYTES;
#pragma unroll
        for (int i = 0; i < 4; i++) {
            int L = tid + (i << 8);
            int row = L >> 3;
            int seg = L & 7;
            uint32_t off = (uint32_t)row * (AST * 2) + seg * 16;
            cp_async16(stage + off,
                       A + (size_t)(rowBase + row) * K + k0 + seg * 8);
            cp_async16(stage + TILE_BYTES + off,
                       Bw + (size_t)(colBase + row) * K + k0 + seg * 8);
        }
        CP_COMMIT();
    };

    issue(0);
    issue(1);
    issue(2);

    for (int ci = 0; ci < NCH; ci++) {
        CP_WAIT(2);
        __syncthreads();
        if (ci + 3 < NCH) issue(ci + 3);
        else CP_COMMIT();

        const uint32_t stage  = smBase + (uint32_t)(ci % NSTAGE) * STAGE_BYTES;
        const uint32_t bBase0 = stage + TILE_BYTES;

#pragma unroll
        for (int ks = 0; ks < 4; ks++) {
            uint32_t Ar[4][4];
#pragma unroll
            for (int mi = 0; mi < 4; mi++) {
                uint32_t addr = stage + (uint32_t)(wm + mi * 16 + aRow) * (AST * 2)
                              + (uint32_t)(ks * 16 + aKo) * 2;
                ldsm_x4(Ar[mi], addr);
            }
            uint32_t Br[2][4];
#pragma unroll
            for (int ni = 0; ni < 2; ni++) {
                uint32_t addr = bBase0 + (uint32_t)(wn + ni * 16 + bNo) * (AST * 2)
                              + (uint32_t)(ks * 16 + bKo) * 2;
                ldsm_x4(Br[ni], addr);
            }
#pragma unroll
            for (int mi = 0; mi < 4; mi++)
#pragma unroll
                for (int j = 0; j < 4; j++)
                    mma_16816_f16(acc[mi][j], Ar[mi],
                                  Br[j >> 1][(j & 1) * 2], Br[j >> 1][(j & 1) * 2 + 1]);
        }
    }

#pragma unroll
    for (int mi = 0; mi < 4; mi++) {
        const int row0 = rowBase + wm + mi * 16 + (lane >> 2);
#pragma unroll
        for (int j = 0; j < 4; j++) {
            const int col = colBase + wn + j * 8 + (lane & 3) * 2;
            *reinterpret_cast<float2*>(C + (size_t)row0 * N + col) =
                make_float2(acc[mi][j][0], acc[mi][j][1]);
            *reinterpret_cast<float2*>(C + (size_t)(row0 + 8) * N + col) =
                make_float2(acc[mi][j][2], acc[mi][j][3]);
        }
    }
}

// ---------------------------------------------------------------------------
// Fused x->fp16 convert + alpha (R8). Block = 16 rows, 512 threads.
// ---------------------------------------------------------------------------
__global__ __launch_bounds__(512) void cvtx_alpha_kernel(
    const float* __restrict__ x, const float* __restrict__ Wa,
    const float* __restrict__ ba, const float* __restrict__ m_gate,
    const float* __restrict__ ascale,
    __half* __restrict__ xh, float* __restrict__ alpha)
{
    extern __shared__ float xs[];        // [16][1024]
    const int tid  = threadIdx.x;
    const int warp = tid >> 5;
    const int lane = tid & 31;
    const int rowBase = blockIdx.x * 16;

    const float4* xg = reinterpret_cast<const float4*>(x + (size_t)rowBase * D_MODEL);
#pragma unroll
    for (int it = 0; it < 8; it++) {
        int i = tid + it * 512;
        float4 v = xg[i];
        reinterpret_cast<float4*>(xs)[i] = v;
        __half2* ph = reinterpret_cast<__half2*>(xh + (size_t)rowBase * D_MODEL + i * 4);
        ph[0] = __half2(__float2half_rn(v.x), __float2half_rn(v.y));
        ph[1] = __half2(__float2half_rn(v.z), __float2half_rn(v.w));
    }
    __syncthreads();

    float wa[32];
#pragma unroll
    for (int i = 0; i < 32; i++)
        wa[i] = Wa[(size_t)warp * D_MODEL + i * 32 + lane];
    const float bw = ba[warp];

#pragma unroll 4
    for (int row = 0; row < 16; row++) {
        const float* xr = xs + row * D_MODEL;
        float s = 0.0f;
#pragma unroll
        for (int i = 0; i < 32; i++)
            s = fmaf(wa[i], xr[i * 32 + lane], s);
#pragma unroll
        for (int off = 16; off; off >>= 1)
            s += __shfl_xor_sync(0xFFFFFFFFu, s, off);
        if (lane == 0) {
            const int r = rowBase + row;
            float sg = __fdividef(1.0f, 1.0f + __expf(-(s + bw)));
            float a = sg * m_gate[r] * ascale[(size_t)r * N_HEADS + warp];
            alpha[(size_t)r * N_HEADS + warp] = fminf(a, ALPHA_MAX);
        }
    }
}

// ---------------------------------------------------------------------------
// Round all 4 weight matrices to fp16 in one launch.
// ---------------------------------------------------------------------------
__global__ __launch_bounds__(256) void cvt4_kernel(
    const float* __restrict__ W0, const float* __restrict__ W1,
    const float* __restrict__ W2, const float* __restrict__ W3,
    __half* __restrict__ out)
{
    const int i = blockIdx.x * 256 + threadIdx.x;
    const int sel = i >> 20;
    const int off = i & ((1 << 20) - 1);
    const float* src = (sel == 0) ? W0 : (sel == 1) ? W1 : (sel == 2) ? W2 : W3;
    out[i] = __float2half_rn(src[off]);
}

// ---------------------------------------------------------------------------
// Sequential fast-weight scan with cp.async smem staging.
// Block = (b,h); 64 threads (thread = d).
// q/k/v/alpha staged in 16-step chunks, double-buffered, 2 chunks in flight
// => global latency fully hidden; per-step reads are conflict-free LDS.
// Score combine of step t-1 piggybacks on step t's barrier (R8 scheme).
// ---------------------------------------------------------------------------
#define SCH 16   // timesteps per staging chunk

__global__ __launch_bounds__(64) void scan_kernel(
    const float* __restrict__ q, const float* __restrict__ k,
    const float* __restrict__ v, const float* __restrict__ alpha,
    __half* __restrict__ yh, int T)
{
    const int bh = blockIdx.x;
    const int b = bh / N_HEADS;
    const int h = bh % N_HEADS;
    const int d = threadIdx.x;
    const int warp = d >> 5;
    const int lane = d & 31;

    __shared__ float sq[2][SCH][D_HEAD];
    __shared__ float sk[2][SCH][D_HEAD];
    __shared__ float sv[2][SCH][D_HEAD];
    __shared__ float sa[2][SCH];
    __shared__ float  sm_ku[2][16][2];
    __shared__ float2 sm_sc[2][2];

    const uint32_t sq_a = smem_u32(sq);
    const uint32_t sk_a = smem_u32(sk);
    const uint32_t sv_a = smem_u32(sv);
    const uint32_t sa_a = smem_u32(sa);

    float U[RANK], Vv[RANK];
#pragma unroll
    for (int r = 0; r < RANK; r++) { U[r] = 0.0f; Vv[r] = 0.0f; }

    const int l4 = lane & 15;
    const int rIdx = ((l4 & 1) << 3) | ((l4 & 2) << 1) | ((l4 & 4) >> 1) | ((l4 & 8) >> 3);

    const size_t strideT = (size_t)N_HEADS * D_HEAD;   // 1024
    const size_t qbase = (size_t)b * T * strideT + (size_t)h * D_HEAD;
    const size_t abase = (size_t)b * T * N_HEADS + h;

    // chunk loader: stages SCH steps of q/k/v (+alpha) into buffer c&1
    auto issue = [&](int c) {
        const int t0 = c * SCH;
        const uint32_t bufB = (uint32_t)(c & 1) * (SCH * D_HEAD * 4);
        // q/k/v: SCH steps x 16 segs (16B) = 256 transfers each; 4/thread
#pragma unroll
        for (int i = 0; i < 4; i++) {
            int L = d + (i << 6);            // 0..255
            int s = L >> 4;
            int seg = L & 15;
            const size_t g = qbase + (size_t)(t0 + s) * strideT + seg * 4;
            const uint32_t so = bufB + (uint32_t)s * (D_HEAD * 4) + seg * 16;
            cp_async16(sq_a + so, q + g);
            cp_async16(sk_a + so, k + g);
            cp_async16(sv_a + so, v + g);
        }
        if (d < SCH)
            cp_async4(sa_a + (uint32_t)(c & 1) * (SCH * 4) + d * 4,
                      alpha + abase + (size_t)(t0 + d) * N_HEADS);
        CP_COMMIT();
    };

    issue(0);
    issue(1);

    float sp0 = 0.f, sp1 = 0.f;
    float vprev = 0.f, kfprev = 0.f;
    size_t yidxprev = 0;
    const int NCHK = T / SCH;               // 128

    for (int c = 0; c < NCHK; c++) {
        CP_WAIT(1);                          // chunk c resident
        __syncthreads();
        const int buf = c & 1;
        const int t0 = c * SCH;

        // first step of chunk: read directly from smem
        float qt = sq[buf][0][d];
        float kt = sk[buf][0][d];
        float vt = sv[buf][0][d];
        float a  = sa[buf][0];

#pragma unroll 4
        for (int s = 0; s < SCH; s++) {
            const int t = t0 + s;
            const int pbuf = t & 1;

            // prefetch next step within this chunk (regs; LDS off-chain)
            float nq = 0.f, nk = 0.f, nv = 0.f, na = 0.f;
            if (s + 1 < SCH) {
                nq = sq[buf][s + 1][d];
                nk = sk[buf][s + 1][d];
                nv = sv[buf][s + 1][d];
                na = sa[buf][s + 1];
            }

            const float ktd = kt * DECAY;
            float p[RANK];
#pragma unroll
            for (int r = 0; r < RANK; r++) p[r] = ktd * U[r];

#pragma unroll
            for (int st = 1, cnt = 8; st <= 8; st <<= 1, cnt >>= 1) {
                const bool hi = (lane & st) != 0;
#pragma unroll
                for (int i = 0; i < cnt; i++) {
                    float lo_v = p[i], hi_v = p[i + cnt];
                    float send = hi ? lo_v : hi_v;
                    float recv = __shfl_xor_sync(0xFFFFFFFFu, send, st);
                    p[i] = (hi ? hi_v : lo_v) + recv;
                }
            }
            float vr = p[0] + __shfl_xor_sync(0xFFFFFFFFu, p[0], 16);

#pragma unroll
            for (int r = 0; r < RANK; r++) { U[r] *= DECAY; Vv[r] *= DECAY; }

            sm_ku[pbuf][rIdx][warp] = vr;
            if (lane == 0) sm_sc[pbuf][warp] = make_float2(sp0, sp1);
            __syncthreads();

            float ku[RANK];
#pragma unroll
            for (int r = 0; r < RANK; r++) {
                float2 t2 = *reinterpret_cast<const float2*>(&sm_ku[pbuf][r][0]);
                ku[r] = t2.x + t2.y;
            }

            const float ak = a * kt;
            const float av = a * vt;
            float kfp[4] = {0.f, 0.f, 0.f, 0.f};
#pragma unroll
            for (int r = 0; r < RANK; r++) {
                float u = fmaf(ak, ku[r], U[r]);
                float w = fmaf(av, ku[r], Vv[r]);
                u -= BETA * fminf(fmaxf(u, -1.0f), 1.0f);
                w -= BETA * fminf(fmaxf(w, -1.0f), 1.0f);
                U[r] = u;
                Vv[r] = w;
                kfp[r & 3] = fmaf(u, w, kfp[r & 3]);
            }
            const float kf = (kfp[0] + kfp[1]) + (kfp[2] + kfp[3]);

            // finalize y(t-1) (scores exchanged at this step's barrier)
            if (t > 0) {
                float2 w0 = sm_sc[pbuf][0];
                float2 w1 = sm_sc[pbuf][1];
                const float S0 = w0.x + w1.x;
                const float S1 = w0.y + w1.y;
                const float m1 = __fdividef(1.0f, 1.0f + __expf(S0 - S1));
                yh[yidxprev] = __float2half_rn((1.0f - m1) * vprev + m1 * kfprev);
            }

            const float qn = qt * 0.125f;
            float s0 = qn * kt;
            float s1 = qn * kf;
#pragma unroll
            for (int off = 16; off; off >>= 1) {
                s0 += __shfl_xor_sync(0xFFFFFFFFu, s0, off);
                s1 += __shfl_xor_sync(0xFFFFFFFFu, s1, off);
            }
            sp0 = s0; sp1 = s1;
            vprev = vt; kfprev = kf;
            yidxprev = qbase + (size_t)t * strideT + d;

            qt = nq; kt = nk; vt = nv; a = na;
        }

        __syncthreads();                     // all reads of buf done
        if (c + 2 < NCHK) issue(c + 2);      // refill this buffer
        else CP_COMMIT();
    }

    // tail: finalize y(T-1)
    if (lane == 0) sm_sc[T & 1][warp] = make_float2(sp0, sp1);
    __syncthreads();
    {
        float2 w0 = sm_sc[T & 1][0];
        float2 w1 = sm_sc[T & 1][1];
        const float S0 = w0.x + w1.x;
        const float S1 = w0.y + w1.y;
        const float m1 = __fdividef(1.0f, 1.0f + __expf(S0 - S1));
        yh[yidxprev] = __float2half_rn((1.0f - m1) * vprev + m1 * kfprev);
    }
}

// ---------------------------------------------------------------------------
// Launch (R8 sequence: single stream)
// ---------------------------------------------------------------------------
extern "C" void kernel_launch(void* const* d_in, const int* in_sizes, int n_in,
                              void* d_out, int out_size)
{
    const float* x      = (const float*)d_in[0];
    const float* m_gate = (const float*)d_in[1];
    const float* ascale = (const float*)d_in[2];
    const float* Wq     = (const float*)d_in[3];
    const float* Wk     = (const float*)d_in[4];
    const float* Wv     = (const float*)d_in[5];
    const float* Wo     = (const float*)d_in[6];
    const float* Wa     = (const float*)d_in[7];
    const float* ba     = (const float*)d_in[8];
    // d_in[9] = mix_logit: cancels in the 2-way softmax; unused.
    float* out = (float*)d_out;

    const int M = in_sizes[1] > 0 ? in_sizes[1] : BT;  // B*T
    const int T = M / BB;

    __half *xh, *wf, *yh;
    float *dq, *dk, *dv, *da;
    cudaGetSymbolAddress((void**)&xh, g_xh);
    cudaGetSymbolAddress((void**)&wf, g_w);
    cudaGetSymbolAddress((void**)&yh, g_yh);
    cudaGetSymbolAddress((void**)&dq, g_q);
    cudaGetSymbolAddress((void**)&dk, g_k);
    cudaGetSymbolAddress((void**)&dv, g_v);
    cudaGetSymbolAddress((void**)&da, g_alpha);

    const int DW = D_MODEL * D_MODEL;

    static bool attr_set = false;
    if (!attr_set) {
        cudaFuncSetAttribute(gemm_f16,
                             cudaFuncAttributeMaxDynamicSharedMemorySize, GEMM_SMEM_BYTES);
        cudaFuncSetAttribute(cvtx_alpha_kernel,
                             cudaFuncAttributeMaxDynamicSharedMemorySize, 16 * D_MODEL * 4);
        attr_set = true;
    }

    cvtx_alpha_kernel<<<M / 16, 512, 16 * D_MODEL * 4>>>(
        x, Wa, ba, m_gate, ascale, xh, da);

    cvt4_kernel<<<(4 * DW) / 256, 256>>>(Wq, Wk, Wv, Wo, wf);

    dim3 gqkv(D_MODEL / GN, M / GM, 3);
    gemm_f16<<<gqkv, 256, GEMM_SMEM_BYTES>>>(xh, wf, dq, dk, dv, M, D_MODEL, D_MODEL);

    scan_kernel<<<BB * N_HEADS, 64>>>(dq, dk, dv, da, yh, T);

    dim3 go(D_MODEL / GN, M / GM, 1);
    gemm_f16<<<go, 256, GEMM_SMEM_BYTES>>>(yh, wf + (size_t)3 * DW,
                                           out, out, out, M, D_MODEL, D_MODEL);
}